// round 1
// baseline (speedup 1.0000x reference)
#include <cuda_runtime.h>
#include <math.h>

#define DT 0.1f
#define EPS_STAT 0.01f

// Per-step constants (data-independent Riccati recursion results).
__device__ float g_k0[64];     // Kalman gain, position component, per est step
__device__ float g_k1[64];     // Kalman gain, velocity component, per est step
__device__ float g_sstd[256];  // sqrt(max(P00, eps^2)) per output step (sx == sy)

// 1-thread setup: run the 2x2 per-axis covariance recursion, store gains & stds.
__global__ void kalman_setup_kernel(const float* __restrict__ sa_p,
                                    const float* __restrict__ so_p,
                                    const float* __restrict__ si_p,
                                    int n_est, int n_pred) {
    if (threadIdx.x != 0 || blockIdx.x != 0) return;
    const float sa = sa_p[0], so = so_p[0], si = si_p[0];
    const float g0 = DT * DT * 0.5f;   // dt^2/2
    const float q00 = sa * sa * (g0 * g0);
    const float q01 = sa * sa * (g0 * DT);
    const float q11 = sa * sa * (DT * DT);
    const float r = so * so;
    const float eps2 = EPS_STAT * EPS_STAT;

    float P00 = si * si, P01 = 0.0f, P11 = si * si;

    for (int k = 0; k < n_est; k++) {
        // predict: P = F P F^T + Q  (2x2 per-axis)
        float nP00 = P00 + 2.0f * DT * P01 + DT * DT * P11 + q00;
        float nP01 = P01 + DT * P11 + q01;
        float nP11 = P11 + q11;
        P00 = nP00; P01 = nP01; P11 = nP11;
        // update: S = P00 + r; K = [P00, P01]/S; Joseph form
        float S  = P00 + r;
        float K0 = P00 / S;
        float K1 = P01 / S;
        g_k0[k] = K0;
        g_k1[k] = K1;
        float omk = 1.0f - K0;
        float A00 = omk * P00;
        float A01 = omk * P01;
        float A10 = P01 - K1 * P00;
        float A11 = P11 - K1 * P01;
        float u00 =  A00 * omk       + r * K0 * K0;
        float u01 = -A00 * K1 + A01  + r * K0 * K1;
        float u11 = -A10 * K1 + A11  + r * K1 * K1;
        P00 = u00; P01 = u01; P11 = u11;
        g_sstd[k] = sqrtf(fmaxf(P00, eps2));
    }
    for (int j = 0; j < n_pred; j++) {
        float nP00 = P00 + 2.0f * DT * P01 + DT * DT * P11 + q00;
        float nP01 = P01 + DT * P11 + q01;
        float nP11 = P11 + q11;
        P00 = nP00; P01 = nP01; P11 = nP11;
        g_sstd[n_est + j] = sqrtf(fmaxf(P00, eps2));
    }
}

template <int BLOCK>
__global__ void __launch_bounds__(BLOCK)
kalman_main_kernel(const float* __restrict__ in, float* __restrict__ out,
                   int B, int n_est, int n_pred) {
    __shared__ float buf[BLOCK * 5];

    const int tid = threadIdx.x;
    const int blockStart = blockIdx.x * BLOCK;
    int b = blockStart + tid;
    const bool valid = (b < B);
    const int bl = valid ? b : (B - 1);  // clamp for loads; stores are masked by region copy

    const float2* __restrict__ zin = reinterpret_cast<const float2*>(in);

    // init: pos = inputs[0], vel = (inputs[1]-inputs[0])/dt
    float2 z0 = zin[bl];
    float2 z1 = zin[(size_t)B + bl];
    float px = z0.x, py = z0.y;
    float vx = (z1.x - z0.x) * (1.0f / DT);
    float vy = (z1.y - z0.y) * (1.0f / DT);

    const long long rowStride = (long long)B * 5;
    const long long outBase = (long long)blockStart * 5;
    const int validInBlock = min(BLOCK, B - blockStart);
    const bool fullBlock = (validInBlock == BLOCK);

    float2 z = z1;  // measurement for est step 0 is inputs[1]
    int t = 0;

    for (int k = 0; k < n_est; k++) {
        // predict mean
        px += DT * vx;
        py += DT * vy;
        // update mean with precomputed gains
        float k0 = g_k0[k], k1 = g_k1[k];
        float yx = z.x - px, yy = z.y - py;
        px += k0 * yx; vx += k1 * yx;
        py += k0 * yy; vy += k1 * yy;
        // prefetch next measurement
        if (k + 1 < n_est) z = zin[(size_t)(k + 2) * B + bl];

        float s = g_sstd[k];
        float* row = buf + tid * 5;
        row[0] = px; row[1] = py; row[2] = s; row[3] = s; row[4] = 0.0f;
        __syncthreads();
        float* dst = out + (long long)t * rowStride + outBase;
        if (fullBlock) {
            float4* d4 = reinterpret_cast<float4*>(dst);
            const float4* s4 = reinterpret_cast<const float4*>(buf);
            for (int i = tid; i < BLOCK * 5 / 4; i += BLOCK) d4[i] = s4[i];
        } else {
            for (int i = tid; i < validInBlock * 5; i += BLOCK) dst[i] = buf[i];
        }
        __syncthreads();
        t++;
    }

    for (int j = 0; j < n_pred; j++) {
        px += DT * vx;
        py += DT * vy;
        float s = g_sstd[n_est + j];
        float* row = buf + tid * 5;
        row[0] = px; row[1] = py; row[2] = s; row[3] = s; row[4] = 0.0f;
        __syncthreads();
        float* dst = out + (long long)t * rowStride + outBase;
        if (fullBlock) {
            float4* d4 = reinterpret_cast<float4*>(dst);
            const float4* s4 = reinterpret_cast<const float4*>(buf);
            for (int i = tid; i < BLOCK * 5 / 4; i += BLOCK) d4[i] = s4[i];
        } else {
            for (int i = tid; i < validInBlock * 5; i += BLOCK) dst[i] = buf[i];
        }
        __syncthreads();
        t++;
    }
}

extern "C" void kernel_launch(void* const* d_in, const int* in_sizes, int n_in,
                              void* d_out, int out_size) {
    const float* inputs  = (const float*)d_in[0];
    const float* sigma_a = (const float*)d_in[1];
    const float* sigma_o = (const float*)d_in[2];
    const float* sigma_i = (const float*)d_in[3];

    const int T_OBS = 10;                       // fixed by the problem shape
    const int B = in_sizes[0] / (T_OBS * 2);    // inputs is (T_OBS, B, 2)
    const int n_est = T_OBS - 1;                // 9
    const int totalSteps = out_size / (B * 5);  // 39
    const int n_pred = totalSteps - n_est;      // 30

    kalman_setup_kernel<<<1, 1>>>(sigma_a, sigma_o, sigma_i, n_est, n_pred);

    constexpr int BLOCK = 256;
    const int grid = (B + BLOCK - 1) / BLOCK;
    kalman_main_kernel<BLOCK><<<grid, BLOCK>>>(inputs, (float*)d_out, B, n_est, n_pred);
}